// round 2
// baseline (speedup 1.0000x reference)
#include <cuda_runtime.h>

// Problem constants
#define CC    512          // channels
#define BSZ   8            // batch
#define HH    128
#define WW    128
#define HWSZ  16384        // H*W
#define NTOT  131072       // B*H*W

// Scratch (device globals: runtime allocation is forbidden)
__device__ float g_qkv[(size_t)3 * CC * NTOT];   // Q,K,V stacked, [3][512][131072]
__device__ float g_att[(size_t)CC * NTOT];       // attention output O, [512][131072]

// ---------------------------------------------------------------------------
// SGEMM: C[m,n] = sum_k A[m,k] * B[k,n],  M=512, K=512, N=131072
// bmode 0: B is xs-layout (per-b base, ldb=HWSZ)   bmode 1: B is [k*NTOT + n]
// cmode 0: C -> g_qkv-style [z][m*NTOT + n]        cmode 1: C -> xs-layout, += addsrc
// blockIdx.z selects A0/A1/A2 (Wq/Wk/Wv) and the z-slice of C (cmode 0).
// 128x128 tile, BK=8, 256 threads, 8x8 per-thread microtile.
// ---------------------------------------------------------------------------
__global__ __launch_bounds__(256) void sgemm_kernel(
    const float* __restrict__ A0, const float* __restrict__ A1,
    const float* __restrict__ A2,
    const float* __restrict__ B, float* __restrict__ C,
    const float* __restrict__ addsrc, int bmode, int cmode)
{
    const int n0 = blockIdx.x * 128;
    const int m0 = blockIdx.y * 128;
    const int z  = blockIdx.z;
    const float* A = (z == 0) ? A0 : (z == 1) ? A1 : A2;

    __shared__ float As[8][128];
    __shared__ float Bs[8][132];

    const int tid   = threadIdx.x;
    const int a_row = tid >> 1;          // 0..127
    const int a_col = (tid & 1) << 2;    // 0 or 4
    const int b_row = tid >> 5;          // 0..7
    const int b_col = (tid & 31) << 2;   // 0..124

    const float* Bp;
    long ldb;
    if (bmode == 0) {
        int bb = n0 >> 14;
        Bp  = B + (((long)bb * CC) << 14) + (n0 & (HWSZ - 1));
        ldb = HWSZ;
    } else {
        Bp  = B + n0;
        ldb = NTOT;
    }

    const int ty = tid >> 4;   // 0..15  (m-sub)
    const int tx = tid & 15;   // 0..15  (n-sub)

    float acc[8][8];
#pragma unroll
    for (int i = 0; i < 8; i++)
#pragma unroll
        for (int j = 0; j < 8; j++) acc[i][j] = 0.0f;

    for (int k0 = 0; k0 < CC; k0 += 8) {
        float4 av = *(const float4*)(A + (long)(m0 + a_row) * CC + (k0 + a_col));
        float4 bv = *(const float4*)(Bp + (long)(k0 + b_row) * ldb + b_col);
        __syncthreads();
        As[a_col + 0][a_row] = av.x;
        As[a_col + 1][a_row] = av.y;
        As[a_col + 2][a_row] = av.z;
        As[a_col + 3][a_row] = av.w;
        *(float4*)&Bs[b_row][b_col] = bv;
        __syncthreads();
#pragma unroll
        for (int kk = 0; kk < 8; kk++) {
            float ar[8], br[8];
#pragma unroll
            for (int i = 0; i < 8; i++) ar[i] = As[kk][ty * 8 + i];
#pragma unroll
            for (int j = 0; j < 8; j++) br[j] = Bs[kk][tx * 8 + j];
#pragma unroll
            for (int i = 0; i < 8; i++)
#pragma unroll
                for (int j = 0; j < 8; j++)
                    acc[i][j] = fmaf(ar[i], br[j], acc[i][j]);
        }
    }

    if (cmode == 0) {
        float* Cp = C + (long)z * CC * NTOT + (long)m0 * NTOT + n0;
#pragma unroll
        for (int i = 0; i < 8; i++) {
            long rb = (long)(ty * 8 + i) * NTOT + tx * 8;
            float4 v0 = make_float4(acc[i][0], acc[i][1], acc[i][2], acc[i][3]);
            float4 v1 = make_float4(acc[i][4], acc[i][5], acc[i][6], acc[i][7]);
            *(float4*)(Cp + rb)     = v0;
            *(float4*)(Cp + rb + 4) = v1;
        }
    } else {
        int bb = n0 >> 14;
        long off = (((long)bb * CC + m0) << 14) + (n0 & (HWSZ - 1));
        float* Cp       = C + off;
        const float* Ad = addsrc + off;
#pragma unroll
        for (int i = 0; i < 8; i++) {
            long rb = (long)(ty * 8 + i) * HWSZ + tx * 8;
            float4 s0 = *(const float4*)(Ad + rb);
            float4 s1 = *(const float4*)(Ad + rb + 4);
            float4 v0 = make_float4(acc[i][0] + s0.x, acc[i][1] + s0.y,
                                    acc[i][2] + s0.z, acc[i][3] + s0.w);
            float4 v1 = make_float4(acc[i][4] + s1.x, acc[i][5] + s1.y,
                                    acc[i][6] + s1.z, acc[i][7] + s1.w);
            *(float4*)(Cp + rb)     = v0;
            *(float4*)(Cp + rb + 4) = v1;
        }
    }
}

// ---------------------------------------------------------------------------
// Attention: one CTA per (b, fix, head). Sequence length 128, dh=64.
// seq_stride/fix_stride: height pass (128, 1), width pass (1, 128).
// S = Q^T K / 8 -> softmax rows -> O = P V, stored back to g_att [c][n].
// ---------------------------------------------------------------------------
#define QK_PAD 132   // 16B-aligned rows (float4 reads in S phase)
#define V_PAD  129   // odd stride => conflict-free lane map in O phase
#define S_PAD  129
#define ATTN_SMEM_FLOATS (2 * 64 * QK_PAD + 64 * V_PAD + 128 * S_PAD)
#define ATTN_SMEM_BYTES  (ATTN_SMEM_FLOATS * 4)

__global__ __launch_bounds__(256) void attn_kernel(
    const float* __restrict__ qkv, float* __restrict__ attout,
    int seq_stride, int fix_stride)
{
    extern __shared__ float sm[];
    float* Qs = sm;                    // [64][QK_PAD]
    float* Ks = Qs + 64 * QK_PAD;      // [64][QK_PAD]
    float* Vs = Ks + 64 * QK_PAD;      // [64][V_PAD]
    float* Ss = Vs + 64 * V_PAD;       // [128][S_PAD]

    const int tid  = threadIdx.x;
    const int fix  = blockIdx.x;   // 0..127 (w for height pass, h for width pass)
    const int head = blockIdx.y;   // 0..7
    const int b    = blockIdx.z;   // 0..7

    const long base = (long)(head * 64) * NTOT + (long)b * HWSZ
                    + (long)fix * fix_stride;
    const float* Qg = qkv + base;
    const float* Kg = qkv + (long)CC * NTOT + base;
    const float* Vg = qkv + 2L * CC * NTOT + base;

#pragma unroll
    for (int it = 0; it < 32; it++) {          // 64*128 / 256
        int idx = it * 256 + tid;
        int d = idx >> 7, s = idx & 127;
        long off = (long)d * NTOT + (long)s * seq_stride;
        Qs[d * QK_PAD + s] = Qg[off];
        Ks[d * QK_PAD + s] = Kg[off];
        Vs[d * V_PAD  + s] = Vg[off];
    }
    __syncthreads();

    // ---- S = Q^T K * dh^-0.5 ----
    {
        const int ty = tid >> 4, tx = tid & 15;
        float acc[8][8];
#pragma unroll
        for (int i = 0; i < 8; i++)
#pragma unroll
            for (int j = 0; j < 8; j++) acc[i][j] = 0.0f;

        for (int d = 0; d < 64; d++) {
            float4 a0 = *(float4*)&Qs[d * QK_PAD + ty * 8];
            float4 a1 = *(float4*)&Qs[d * QK_PAD + ty * 8 + 4];
            float4 b0 = *(float4*)&Ks[d * QK_PAD + tx * 8];
            float4 b1 = *(float4*)&Ks[d * QK_PAD + tx * 8 + 4];
            float a[8] = {a0.x, a0.y, a0.z, a0.w, a1.x, a1.y, a1.z, a1.w};
            float bb[8] = {b0.x, b0.y, b0.z, b0.w, b1.x, b1.y, b1.z, b1.w};
#pragma unroll
            for (int i = 0; i < 8; i++)
#pragma unroll
                for (int j = 0; j < 8; j++)
                    acc[i][j] = fmaf(a[i], bb[j], acc[i][j]);
        }
#pragma unroll
        for (int i = 0; i < 8; i++)
#pragma unroll
            for (int j = 0; j < 8; j++)
                Ss[(ty * 8 + i) * S_PAD + tx * 8 + j] = acc[i][j] * 0.125f;
    }
    __syncthreads();

    // ---- softmax over rows (key axis) ----
    if (tid < 128) {
        float* row = Ss + tid * S_PAD;
        float mx = row[0];
        for (int j = 1; j < 128; j++) mx = fmaxf(mx, row[j]);
        float s = 0.0f;
        for (int j = 0; j < 128; j++) {
            float e = __expf(row[j] - mx);
            row[j] = e;
            s += e;
        }
        float inv = 1.0f / s;
        for (int j = 0; j < 128; j++) row[j] *= inv;
    }
    __syncthreads();

    // ---- O[d][i] = sum_j P[i][j] * V[d][j] ----
    {
        const int tx4 = tid & 15;   // d = tx4 + di*16  (conflict-free V reads)
        const int g16 = tid >> 4;   // i = g16*8 + ii   (broadcast P reads)
        float acc[4][8];
#pragma unroll
        for (int di = 0; di < 4; di++)
#pragma unroll
            for (int ii = 0; ii < 8; ii++) acc[di][ii] = 0.0f;

        for (int j = 0; j < 128; j++) {
            float v[4], p[8];
#pragma unroll
            for (int di = 0; di < 4; di++)
                v[di] = Vs[(tx4 + di * 16) * V_PAD + j];
#pragma unroll
            for (int ii = 0; ii < 8; ii++)
                p[ii] = Ss[(g16 * 8 + ii) * S_PAD + j];
#pragma unroll
            for (int di = 0; di < 4; di++)
#pragma unroll
                for (int ii = 0; ii < 8; ii++)
                    acc[di][ii] = fmaf(v[di], p[ii], acc[di][ii]);
        }
#pragma unroll
        for (int di = 0; di < 4; di++) {
            int d = tx4 + di * 16;
            long cbase = (long)(head * 64 + d) * NTOT + (long)b * HWSZ
                       + (long)fix * fix_stride;
#pragma unroll
            for (int ii = 0; ii < 8; ii++) {
                int i = g16 * 8 + ii;
                attout[cbase + (long)i * seq_stride] = acc[di][ii];
            }
        }
    }
}

// ---------------------------------------------------------------------------
extern "C" void kernel_launch(void* const* d_in, const int* in_sizes, int n_in,
                              void* d_out, int out_size)
{
    const float* xs   = (const float*)d_in[0];
    const float* Wq_h = (const float*)d_in[1];
    const float* Wk_h = (const float*)d_in[2];
    const float* Wv_h = (const float*)d_in[3];
    const float* Wo_h = (const float*)d_in[4];
    const float* Wq_w = (const float*)d_in[5];
    const float* Wk_w = (const float*)d_in[6];
    const float* Wv_w = (const float*)d_in[7];
    const float* Wo_w = (const float*)d_in[8];
    float* out = (float*)d_out;

    float *qkv = nullptr, *att = nullptr;
    cudaGetSymbolAddress((void**)&qkv, g_qkv);
    cudaGetSymbolAddress((void**)&att, g_att);

    cudaFuncSetAttribute(attn_kernel,
                         cudaFuncAttributeMaxDynamicSharedMemorySize,
                         ATTN_SMEM_BYTES);

    dim3 gproj(NTOT / 128, CC / 128, 3);
    dim3 gout (NTOT / 128, CC / 128, 1);
    dim3 gattn(128, 8, 8);

    // ---- height branch: sequence along H (stride 128), fixed w (stride 1) ----
    sgemm_kernel<<<gproj, 256>>>(Wq_h, Wk_h, Wv_h, xs, qkv, nullptr, 0, 0);
    attn_kernel<<<gattn, 256, ATTN_SMEM_BYTES>>>(qkv, att, 128, 1);
    sgemm_kernel<<<gout, 256>>>(Wo_h, Wo_h, Wo_h, att, out, xs, 1, 1);

    // ---- width branch: sequence along W (stride 1), fixed h (stride 128) ----
    sgemm_kernel<<<gproj, 256>>>(Wq_w, Wk_w, Wv_w, xs, qkv, nullptr, 0, 0);
    attn_kernel<<<gattn, 256, ATTN_SMEM_BYTES>>>(qkv, att, 1, 128);
    sgemm_kernel<<<gout, 256>>>(Wo_w, Wo_w, Wo_w, att, out, out, 1, 1);
}

// round 3
// speedup vs baseline: 1.9588x; 1.9588x over previous
#include <cuda_runtime.h>

// Problem constants
#define CC    512          // channels
#define BSZ   8            // batch
#define HH    128
#define WW    128
#define HWSZ  16384        // H*W
#define NTOT  131072       // B*H*W

// Scratch (device globals: runtime allocation is forbidden)
__device__ float g_qkv[(size_t)3 * CC * NTOT];   // Q,K,V stacked, [3][512][131072]
__device__ float g_att[(size_t)CC * NTOT];       // attention output O, [512][131072]

__device__ __forceinline__ unsigned f2tf32(float x) {
    unsigned r;
    asm("cvt.rna.tf32.f32 %0, %1;" : "=r"(r) : "f"(x));
    return r;
}

// ---------------------------------------------------------------------------
// TF32 tensor-core GEMM: C[m,n] = sum_k A[m,k]*B[k,n], M=512,K=512,N=131072
// bmode 0: B is xs-layout (per-b base, ldb=HWSZ)   bmode 1: B is [k*NTOT+n]
// cmode 0: C -> g_qkv-style [z][m*NTOT+n]          cmode 1: C -> xs-layout, += addsrc
// 128x128 CTA tile, BK=32, 256 threads, 8 warps (2 x 4), warp tile 64x32,
// mma.sync m16n8k8 tf32 with fp32 accumulate.
// ---------------------------------------------------------------------------
#define BM 128
#define BN 128
#define BK 32
#define SPAD 136   // stride pad: 136 % 32 == 8 -> qid groups hit disjoint banks

__global__ __launch_bounds__(256) void tgemm_kernel(
    const float* __restrict__ A0, const float* __restrict__ A1,
    const float* __restrict__ A2,
    const float* __restrict__ B, float* __restrict__ C,
    const float* __restrict__ addsrc, int bmode, int cmode)
{
    const int n0 = blockIdx.x * BN;
    const int m0 = blockIdx.y * BM;
    const int z  = blockIdx.z;
    const float* A = (z == 0) ? A0 : (z == 1) ? A1 : A2;

    __shared__ unsigned As[BK][SPAD];   // [k][m], tf32 bits
    __shared__ unsigned Bs[BK][SPAD];   // [k][n], tf32 bits

    const int tid  = threadIdx.x;
    const int lane = tid & 31;
    const int warp = tid >> 5;
    const int grp  = lane >> 2;    // 0..7
    const int qid  = lane & 3;     // 0..3
    const int mw   = (warp >> 2) * 64;   // warp M offset: 0 or 64
    const int nw   = (warp & 3) * 32;    // warp N offset: 0,32,64,96

    // global-load lane mapping
    const int am = tid >> 1;            // 0..127
    const int ak = (tid & 1) * 4;       // 0 or 4
    const int bk = tid >> 5;            // 0..7
    const int bn = (tid & 31) * 4;      // 0..124

    const float* Bp;
    long ldb;
    if (bmode == 0) {
        int bb = n0 >> 14;
        Bp  = B + (((long)bb * CC) << 14) + (n0 & (HWSZ - 1));
        ldb = HWSZ;
    } else {
        Bp  = B + n0;
        ldb = NTOT;
    }
    const float* Ap = A + (long)(m0 + am) * CC + ak;

    float acc[4][4][4];
#pragma unroll
    for (int mi = 0; mi < 4; mi++)
#pragma unroll
        for (int ni = 0; ni < 4; ni++)
#pragma unroll
            for (int r = 0; r < 4; r++) acc[mi][ni][r] = 0.0f;

    float4 ra[4], rb[4];
#pragma unroll
    for (int r = 0; r < 4; r++) {
        ra[r] = *(const float4*)(Ap + 8 * r);
        rb[r] = *(const float4*)(Bp + (long)(bk + 8 * r) * ldb + bn);
    }

    for (int k0 = 0; k0 < CC; k0 += BK) {
        // stage regs -> smem (convert to tf32 RNA)
#pragma unroll
        for (int r = 0; r < 4; r++) {
            As[ak + 8 * r + 0][am] = f2tf32(ra[r].x);
            As[ak + 8 * r + 1][am] = f2tf32(ra[r].y);
            As[ak + 8 * r + 2][am] = f2tf32(ra[r].z);
            As[ak + 8 * r + 3][am] = f2tf32(ra[r].w);
            unsigned bu0 = f2tf32(rb[r].x), bu1 = f2tf32(rb[r].y);
            unsigned bu2 = f2tf32(rb[r].z), bu3 = f2tf32(rb[r].w);
            *(uint4*)&Bs[bk + 8 * r][bn] = make_uint4(bu0, bu1, bu2, bu3);
        }
        __syncthreads();

        // prefetch next K-slab
        if (k0 + BK < CC) {
#pragma unroll
            for (int r = 0; r < 4; r++) {
                ra[r] = *(const float4*)(Ap + (k0 + BK) + 8 * r);
                rb[r] = *(const float4*)(Bp + (long)(k0 + BK + bk + 8 * r) * ldb + bn);
            }
        }

        // compute: 4 k-steps of 8
#pragma unroll
        for (int ks = 0; ks < 4; ks++) {
            const int kb = ks * 8;
            unsigned a[4][4], b[4][2];
#pragma unroll
            for (int mi = 0; mi < 4; mi++) {
                int mr = mw + mi * 16 + grp;
                a[mi][0] = As[kb + qid][mr];
                a[mi][1] = As[kb + qid][mr + 8];
                a[mi][2] = As[kb + qid + 4][mr];
                a[mi][3] = As[kb + qid + 4][mr + 8];
            }
#pragma unroll
            for (int ni = 0; ni < 4; ni++) {
                int nc = nw + ni * 8 + grp;
                b[ni][0] = Bs[kb + qid][nc];
                b[ni][1] = Bs[kb + qid + 4][nc];
            }
#pragma unroll
            for (int mi = 0; mi < 4; mi++)
#pragma unroll
                for (int ni = 0; ni < 4; ni++) {
                    asm volatile(
                        "mma.sync.aligned.m16n8k8.row.col.f32.tf32.tf32.f32 "
                        "{%0,%1,%2,%3}, {%4,%5,%6,%7}, {%8,%9}, {%0,%1,%2,%3};\n"
                        : "+f"(acc[mi][ni][0]), "+f"(acc[mi][ni][1]),
                          "+f"(acc[mi][ni][2]), "+f"(acc[mi][ni][3])
                        : "r"(a[mi][0]), "r"(a[mi][1]), "r"(a[mi][2]), "r"(a[mi][3]),
                          "r"(b[ni][0]), "r"(b[ni][1]));
                }
        }
        __syncthreads();
    }

    // epilogue
    const int cq = 2 * qid;
    if (cmode == 0) {
        float* Cp = C + (long)z * CC * NTOT + (long)m0 * NTOT + n0;
#pragma unroll
        for (int mi = 0; mi < 4; mi++) {
            int r0 = mw + mi * 16 + grp;
#pragma unroll
            for (int ni = 0; ni < 4; ni++) {
                int col = nw + ni * 8 + cq;
                *(float2*)(Cp + (long)r0 * NTOT + col) =
                    make_float2(acc[mi][ni][0], acc[mi][ni][1]);
                *(float2*)(Cp + (long)(r0 + 8) * NTOT + col) =
                    make_float2(acc[mi][ni][2], acc[mi][ni][3]);
            }
        }
    } else {
        int bb = n0 >> 14;
        long off = (((long)bb * CC + m0) << 14) + (n0 & (HWSZ - 1));
        float* Cp       = C + off;
        const float* Ad = addsrc + off;
#pragma unroll
        for (int mi = 0; mi < 4; mi++) {
            int r0 = mw + mi * 16 + grp;
#pragma unroll
            for (int ni = 0; ni < 4; ni++) {
                int col = nw + ni * 8 + cq;
                long o0 = (long)r0 * HWSZ + col;
                long o1 = (long)(r0 + 8) * HWSZ + col;
                float2 s0 = *(const float2*)(Ad + o0);
                float2 s1 = *(const float2*)(Ad + o1);
                *(float2*)(Cp + o0) = make_float2(acc[mi][ni][0] + s0.x,
                                                  acc[mi][ni][1] + s0.y);
                *(float2*)(Cp + o1) = make_float2(acc[mi][ni][2] + s1.x,
                                                  acc[mi][ni][3] + s1.y);
            }
        }
    }
}

// ---------------------------------------------------------------------------
// Attention: one CTA per (b, fix, head). Sequence length 128, dh=64. (fp32)
// ---------------------------------------------------------------------------
#define QK_PAD 132
#define V_PAD  129
#define S_PAD  129
#define ATTN_SMEM_FLOATS (2 * 64 * QK_PAD + 64 * V_PAD + 128 * S_PAD)
#define ATTN_SMEM_BYTES  (ATTN_SMEM_FLOATS * 4)

__global__ __launch_bounds__(256) void attn_kernel(
    const float* __restrict__ qkv, float* __restrict__ attout,
    int seq_stride, int fix_stride)
{
    extern __shared__ float sm[];
    float* Qs = sm;
    float* Ks = Qs + 64 * QK_PAD;
    float* Vs = Ks + 64 * QK_PAD;
    float* Ss = Vs + 64 * V_PAD;

    const int tid  = threadIdx.x;
    const int fix  = blockIdx.x;
    const int head = blockIdx.y;
    const int b    = blockIdx.z;

    const long base = (long)(head * 64) * NTOT + (long)b * HWSZ
                    + (long)fix * fix_stride;
    const float* Qg = qkv + base;
    const float* Kg = qkv + (long)CC * NTOT + base;
    const float* Vg = qkv + 2L * CC * NTOT + base;

#pragma unroll
    for (int it = 0; it < 32; it++) {
        int idx = it * 256 + tid;
        int d = idx >> 7, s = idx & 127;
        long off = (long)d * NTOT + (long)s * seq_stride;
        Qs[d * QK_PAD + s] = Qg[off];
        Ks[d * QK_PAD + s] = Kg[off];
        Vs[d * V_PAD  + s] = Vg[off];
    }
    __syncthreads();

    {
        const int ty = tid >> 4, tx = tid & 15;
        float acc[8][8];
#pragma unroll
        for (int i = 0; i < 8; i++)
#pragma unroll
            for (int j = 0; j < 8; j++) acc[i][j] = 0.0f;

        for (int d = 0; d < 64; d++) {
            float4 a0 = *(float4*)&Qs[d * QK_PAD + ty * 8];
            float4 a1 = *(float4*)&Qs[d * QK_PAD + ty * 8 + 4];
            float4 b0 = *(float4*)&Ks[d * QK_PAD + tx * 8];
            float4 b1 = *(float4*)&Ks[d * QK_PAD + tx * 8 + 4];
            float a[8] = {a0.x, a0.y, a0.z, a0.w, a1.x, a1.y, a1.z, a1.w};
            float bb[8] = {b0.x, b0.y, b0.z, b0.w, b1.x, b1.y, b1.z, b1.w};
#pragma unroll
            for (int i = 0; i < 8; i++)
#pragma unroll
                for (int j = 0; j < 8; j++)
                    acc[i][j] = fmaf(a[i], bb[j], acc[i][j]);
        }
#pragma unroll
        for (int i = 0; i < 8; i++)
#pragma unroll
            for (int j = 0; j < 8; j++)
                Ss[(ty * 8 + i) * S_PAD + tx * 8 + j] = acc[i][j] * 0.125f;
    }
    __syncthreads();

    if (tid < 128) {
        float* row = Ss + tid * S_PAD;
        float mx = row[0];
        for (int j = 1; j < 128; j++) mx = fmaxf(mx, row[j]);
        float s = 0.0f;
        for (int j = 0; j < 128; j++) {
            float e = __expf(row[j] - mx);
            row[j] = e;
            s += e;
        }
        float inv = 1.0f / s;
        for (int j = 0; j < 128; j++) row[j] *= inv;
    }
    __syncthreads();

    {
        const int tx4 = tid & 15;
        const int g16 = tid >> 4;
        float acc[4][8];
#pragma unroll
        for (int di = 0; di < 4; di++)
#pragma unroll
            for (int ii = 0; ii < 8; ii++) acc[di][ii] = 0.0f;

        for (int j = 0; j < 128; j++) {
            float v[4], p[8];
#pragma unroll
            for (int di = 0; di < 4; di++)
                v[di] = Vs[(tx4 + di * 16) * V_PAD + j];
#pragma unroll
            for (int ii = 0; ii < 8; ii++)
                p[ii] = Ss[(g16 * 8 + ii) * S_PAD + j];
#pragma unroll
            for (int di = 0; di < 4; di++)
#pragma unroll
                for (int ii = 0; ii < 8; ii++)
                    acc[di][ii] = fmaf(v[di], p[ii], acc[di][ii]);
        }
#pragma unroll
        for (int di = 0; di < 4; di++) {
            int d = tx4 + di * 16;
            long cbase = (long)(head * 64 + d) * NTOT + (long)b * HWSZ
                       + (long)fix * fix_stride;
#pragma unroll
            for (int ii = 0; ii < 8; ii++) {
                int i = g16 * 8 + ii;
                attout[cbase + (long)i * seq_stride] = acc[di][ii];
            }
        }
    }
}

// ---------------------------------------------------------------------------
extern "C" void kernel_launch(void* const* d_in, const int* in_sizes, int n_in,
                              void* d_out, int out_size)
{
    const float* xs   = (const float*)d_in[0];
    const float* Wq_h = (const float*)d_in[1];
    const float* Wk_h = (const float*)d_in[2];
    const float* Wv_h = (const float*)d_in[3];
    const float* Wo_h = (const float*)d_in[4];
    const float* Wq_w = (const float*)d_in[5];
    const float* Wk_w = (const float*)d_in[6];
    const float* Wv_w = (const float*)d_in[7];
    const float* Wo_w = (const float*)d_in[8];
    float* out = (float*)d_out;

    float *qkv = nullptr, *att = nullptr;
    cudaGetSymbolAddress((void**)&qkv, g_qkv);
    cudaGetSymbolAddress((void**)&att, g_att);

    cudaFuncSetAttribute(attn_kernel,
                         cudaFuncAttributeMaxDynamicSharedMemorySize,
                         ATTN_SMEM_BYTES);

    dim3 gproj(NTOT / BN, CC / BM, 3);
    dim3 gout (NTOT / BN, CC / BM, 1);
    dim3 gattn(128, 8, 8);

    // ---- height branch: sequence along H (stride 128), fixed w (stride 1) ----
    tgemm_kernel<<<gproj, 256>>>(Wq_h, Wk_h, Wv_h, xs, qkv, nullptr, 0, 0);
    attn_kernel<<<gattn, 256, ATTN_SMEM_BYTES>>>(qkv, att, 128, 1);
    tgemm_kernel<<<gout, 256>>>(Wo_h, Wo_h, Wo_h, att, out, xs, 1, 1);

    // ---- width branch: sequence along W (stride 1), fixed h (stride 128) ----
    tgemm_kernel<<<gproj, 256>>>(Wq_w, Wk_w, Wv_w, xs, qkv, nullptr, 0, 0);
    attn_kernel<<<gattn, 256, ATTN_SMEM_BYTES>>>(qkv, att, 1, 128);
    tgemm_kernel<<<gout, 256>>>(Wo_w, Wo_w, Wo_w, att, out, out, 1, 1);
}

// round 4
// speedup vs baseline: 2.6902x; 1.3733x over previous
#include <cuda_runtime.h>

// Problem constants
#define CC    512          // channels
#define BSZ   8            // batch
#define HH    128
#define WW    128
#define HWSZ  16384        // H*W
#define NTOT  131072       // B*H*W

// Scratch (device globals: runtime allocation is forbidden)
__device__ float g_qkv[(size_t)3 * CC * NTOT];   // Q,K,V stacked
__device__ float g_att[(size_t)CC * NTOT];       // attention output
__device__ float g_tmp[(size_t)CC * NTOT];       // transposed xs / oh_t

__device__ __forceinline__ unsigned f2tf32(float x) {
    unsigned r;
    asm("cvt.rna.tf32.f32 %0, %1;" : "=r"(r) : "f"(x));
    return r;
}

// ---------------------------------------------------------------------------
// HW-plane transpose: dst[plane][j][i] = src[plane][i][j]  (+ optional add in
// dst-index space: dst = addsrc + T(src)). plane = b*C + c, 128x128 planes.
// grid (4,4,B*C), block (32,8).
// ---------------------------------------------------------------------------
__global__ __launch_bounds__(256) void transpose_hw_kernel(
    const float* __restrict__ src, float* __restrict__ dst,
    const float* __restrict__ addsrc)
{
    __shared__ float t[32][33];
    const int i0 = blockIdx.x * 32;       // src row block
    const int j0 = blockIdx.y * 32;       // src col block
    const long plane = (long)blockIdx.z * HWSZ;
    const int tx = threadIdx.x, ty = threadIdx.y;

#pragma unroll
    for (int r = 0; r < 4; r++)
        t[ty + 8 * r][tx] = src[plane + (long)(i0 + ty + 8 * r) * 128 + j0 + tx];
    __syncthreads();
#pragma unroll
    for (int r = 0; r < 4; r++) {
        long o = plane + (long)(j0 + ty + 8 * r) * 128 + i0 + tx;
        float v = t[tx][ty + 8 * r];
        if (addsrc) v += addsrc[o];
        dst[o] = v;
    }
}

// ---------------------------------------------------------------------------
// TF32 tensor-core GEMM (unchanged core from R2): M=512, K=512, N=131072
// bmode 0: B xs-layout (per-b base, ldb=HWSZ)   bmode 1: B is [k*NTOT+n]
// cmode 0: C -> [z][m*NTOT+n]   cmode 1: C -> xs-layout (+= addsrc if non-null)
// ---------------------------------------------------------------------------
#define BM 128
#define BN 128
#define BK 32
#define SPAD 136

__global__ __launch_bounds__(256) void tgemm_kernel(
    const float* __restrict__ A0, const float* __restrict__ A1,
    const float* __restrict__ A2,
    const float* __restrict__ B, float* __restrict__ C,
    const float* __restrict__ addsrc, int bmode, int cmode)
{
    const int n0 = blockIdx.x * BN;
    const int m0 = blockIdx.y * BM;
    const int z  = blockIdx.z;
    const float* A = (z == 0) ? A0 : (z == 1) ? A1 : A2;

    __shared__ unsigned As[BK][SPAD];
    __shared__ unsigned Bs[BK][SPAD];

    const int tid  = threadIdx.x;
    const int lane = tid & 31;
    const int warp = tid >> 5;
    const int grp  = lane >> 2;
    const int qid  = lane & 3;
    const int mw   = (warp >> 2) * 64;
    const int nw   = (warp & 3) * 32;

    const int am = tid >> 1;
    const int ak = (tid & 1) * 4;
    const int bk = tid >> 5;
    const int bn = (tid & 31) * 4;

    const float* Bp;
    long ldb;
    if (bmode == 0) {
        int bb = n0 >> 14;
        Bp  = B + (((long)bb * CC) << 14) + (n0 & (HWSZ - 1));
        ldb = HWSZ;
    } else {
        Bp  = B + n0;
        ldb = NTOT;
    }
    const float* Ap = A + (long)(m0 + am) * CC + ak;

    float acc[4][4][4];
#pragma unroll
    for (int mi = 0; mi < 4; mi++)
#pragma unroll
        for (int ni = 0; ni < 4; ni++)
#pragma unroll
            for (int r = 0; r < 4; r++) acc[mi][ni][r] = 0.0f;

    float4 ra[4], rb[4];
#pragma unroll
    for (int r = 0; r < 4; r++) {
        ra[r] = *(const float4*)(Ap + 8 * r);
        rb[r] = *(const float4*)(Bp + (long)(bk + 8 * r) * ldb + bn);
    }

    for (int k0 = 0; k0 < CC; k0 += BK) {
#pragma unroll
        for (int r = 0; r < 4; r++) {
            As[ak + 8 * r + 0][am] = f2tf32(ra[r].x);
            As[ak + 8 * r + 1][am] = f2tf32(ra[r].y);
            As[ak + 8 * r + 2][am] = f2tf32(ra[r].z);
            As[ak + 8 * r + 3][am] = f2tf32(ra[r].w);
            unsigned bu0 = f2tf32(rb[r].x), bu1 = f2tf32(rb[r].y);
            unsigned bu2 = f2tf32(rb[r].z), bu3 = f2tf32(rb[r].w);
            *(uint4*)&Bs[bk + 8 * r][bn] = make_uint4(bu0, bu1, bu2, bu3);
        }
        __syncthreads();

        if (k0 + BK < CC) {
#pragma unroll
            for (int r = 0; r < 4; r++) {
                ra[r] = *(const float4*)(Ap + (k0 + BK) + 8 * r);
                rb[r] = *(const float4*)(Bp + (long)(k0 + BK + bk + 8 * r) * ldb + bn);
            }
        }

#pragma unroll
        for (int ks = 0; ks < 4; ks++) {
            const int kb = ks * 8;
            unsigned a[4][4], b[4][2];
#pragma unroll
            for (int mi = 0; mi < 4; mi++) {
                int mr = mw + mi * 16 + grp;
                a[mi][0] = As[kb + qid][mr];
                a[mi][1] = As[kb + qid][mr + 8];
                a[mi][2] = As[kb + qid + 4][mr];
                a[mi][3] = As[kb + qid + 4][mr + 8];
            }
#pragma unroll
            for (int ni = 0; ni < 4; ni++) {
                int nc = nw + ni * 8 + grp;
                b[ni][0] = Bs[kb + qid][nc];
                b[ni][1] = Bs[kb + qid + 4][nc];
            }
#pragma unroll
            for (int mi = 0; mi < 4; mi++)
#pragma unroll
                for (int ni = 0; ni < 4; ni++) {
                    asm volatile(
                        "mma.sync.aligned.m16n8k8.row.col.f32.tf32.tf32.f32 "
                        "{%0,%1,%2,%3}, {%4,%5,%6,%7}, {%8,%9}, {%0,%1,%2,%3};\n"
                        : "+f"(acc[mi][ni][0]), "+f"(acc[mi][ni][1]),
                          "+f"(acc[mi][ni][2]), "+f"(acc[mi][ni][3])
                        : "r"(a[mi][0]), "r"(a[mi][1]), "r"(a[mi][2]), "r"(a[mi][3]),
                          "r"(b[ni][0]), "r"(b[ni][1]));
                }
        }
        __syncthreads();
    }

    const int cq = 2 * qid;
    if (cmode == 0) {
        float* Cp = C + (long)z * CC * NTOT + (long)m0 * NTOT + n0;
#pragma unroll
        for (int mi = 0; mi < 4; mi++) {
            int r0 = mw + mi * 16 + grp;
#pragma unroll
            for (int ni = 0; ni < 4; ni++) {
                int col = nw + ni * 8 + cq;
                *(float2*)(Cp + (long)r0 * NTOT + col) =
                    make_float2(acc[mi][ni][0], acc[mi][ni][1]);
                *(float2*)(Cp + (long)(r0 + 8) * NTOT + col) =
                    make_float2(acc[mi][ni][2], acc[mi][ni][3]);
            }
        }
    } else {
        int bb = n0 >> 14;
        long off = (((long)bb * CC + m0) << 14) + (n0 & (HWSZ - 1));
        float* Cp = C + off;
        const float* Ad = addsrc ? (addsrc + off) : nullptr;
#pragma unroll
        for (int mi = 0; mi < 4; mi++) {
            int r0 = mw + mi * 16 + grp;
#pragma unroll
            for (int ni = 0; ni < 4; ni++) {
                int col = nw + ni * 8 + cq;
                long o0 = (long)r0 * HWSZ + col;
                long o1 = (long)(r0 + 8) * HWSZ + col;
                float2 v0 = make_float2(acc[mi][ni][0], acc[mi][ni][1]);
                float2 v1 = make_float2(acc[mi][ni][2], acc[mi][ni][3]);
                if (Ad) {
                    float2 s0 = *(const float2*)(Ad + o0);
                    float2 s1 = *(const float2*)(Ad + o1);
                    v0.x += s0.x; v0.y += s0.y;
                    v1.x += s1.x; v1.y += s1.y;
                }
                *(float2*)(Cp + o0) = v0;
                *(float2*)(Cp + o1) = v1;
            }
        }
    }
}

// ---------------------------------------------------------------------------
// Tensor-core attention. Requires contiguous sequence (stride 1), fix stride
// 128. One CTA per (fix, head, b), 256 threads. S=Q^T K (tf32 MMA), warp
// softmax, O^T = V P^T (tf32 MMA), coalesced store.
// ---------------------------------------------------------------------------
#define PKM 136   // [k][m] smem layouts (A/B frag reads: qid*8+grp unique)
#define PMK 132   // [m][k] smem layouts (frag reads: grp*4+qid unique)
#define ATTN_SMEM_U32 (2 * 64 * PKM + 64 * PMK + 128 * PMK)
#define ATTN_SMEM_BYTES (ATTN_SMEM_U32 * 4)

__global__ __launch_bounds__(256) void attn_tc_kernel(
    const float* __restrict__ qkv, float* __restrict__ attout)
{
    extern __shared__ unsigned smu[];
    unsigned* Qs = smu;                 // [64][PKM] tf32 (later reused as Os)
    unsigned* Ks = Qs + 64 * PKM;       // [64][PKM] tf32
    unsigned* Vs = Ks + 64 * PKM;       // [64][PMK] tf32
    unsigned* Ss = Vs + 64 * PMK;       // [128][PMK] fp32 S -> tf32 P

    const int tid  = threadIdx.x;
    const int lane = tid & 31;
    const int warp = tid >> 5;
    const int grp  = lane >> 2;
    const int qid  = lane & 3;

    const int fix  = blockIdx.x;
    const int head = blockIdx.y;
    const int b    = blockIdx.z;

    const long base = (long)(head * 64) * NTOT + (long)b * HWSZ + (long)fix * 128;
    const float* Qg = qkv + base;
    const float* Kg = qkv + (long)CC * NTOT + base;
    const float* Vg = qkv + 2L * CC * NTOT + base;

    // coalesced loads (seq contiguous), convert to tf32
#pragma unroll
    for (int it = 0; it < 32; it++) {
        int idx = it * 256 + tid;
        int d = idx >> 7, s = idx & 127;
        long off = (long)d * NTOT + s;
        Qs[d * PKM + s] = f2tf32(Qg[off]);
        Ks[d * PKM + s] = f2tf32(Kg[off]);
        Vs[d * PMK + s] = f2tf32(Vg[off]);
    }
    __syncthreads();

    // ---- S[i][j] = sum_d Q[d][i] K[d][j], warps tile 128x128 as 4x2 of 32x64
    {
        const int mw = (warp >> 1) * 32;
        const int nw = (warp & 1) * 64;
        float acc[2][8][4];
#pragma unroll
        for (int mi = 0; mi < 2; mi++)
#pragma unroll
            for (int ni = 0; ni < 8; ni++)
#pragma unroll
                for (int r = 0; r < 4; r++) acc[mi][ni][r] = 0.0f;

#pragma unroll
        for (int ks = 0; ks < 8; ks++) {
            const int kb = ks * 8;
            unsigned a[2][4], bf[8][2];
#pragma unroll
            for (int mi = 0; mi < 2; mi++) {
                int mr = mw + mi * 16 + grp;
                a[mi][0] = Qs[(kb + qid) * PKM + mr];
                a[mi][1] = Qs[(kb + qid) * PKM + mr + 8];
                a[mi][2] = Qs[(kb + qid + 4) * PKM + mr];
                a[mi][3] = Qs[(kb + qid + 4) * PKM + mr + 8];
            }
#pragma unroll
            for (int ni = 0; ni < 8; ni++) {
                int nc = nw + ni * 8 + grp;
                bf[ni][0] = Ks[(kb + qid) * PKM + nc];
                bf[ni][1] = Ks[(kb + qid + 4) * PKM + nc];
            }
#pragma unroll
            for (int mi = 0; mi < 2; mi++)
#pragma unroll
                for (int ni = 0; ni < 8; ni++) {
                    asm volatile(
                        "mma.sync.aligned.m16n8k8.row.col.f32.tf32.tf32.f32 "
                        "{%0,%1,%2,%3}, {%4,%5,%6,%7}, {%8,%9}, {%0,%1,%2,%3};\n"
                        : "+f"(acc[mi][ni][0]), "+f"(acc[mi][ni][1]),
                          "+f"(acc[mi][ni][2]), "+f"(acc[mi][ni][3])
                        : "r"(a[mi][0]), "r"(a[mi][1]), "r"(a[mi][2]), "r"(a[mi][3]),
                          "r"(bf[ni][0]), "r"(bf[ni][1]));
                }
        }
        // store scaled fp32 S
#pragma unroll
        for (int mi = 0; mi < 2; mi++) {
            int r0 = mw + mi * 16 + grp;
#pragma unroll
            for (int ni = 0; ni < 8; ni++) {
                int col = nw + ni * 8 + 2 * qid;
                Ss[r0 * PMK + col]           = __float_as_uint(acc[mi][ni][0] * 0.125f);
                Ss[r0 * PMK + col + 1]       = __float_as_uint(acc[mi][ni][1] * 0.125f);
                Ss[(r0 + 8) * PMK + col]     = __float_as_uint(acc[mi][ni][2] * 0.125f);
                Ss[(r0 + 8) * PMK + col + 1] = __float_as_uint(acc[mi][ni][3] * 0.125f);
            }
        }
    }
    __syncthreads();

    // ---- softmax: warp w handles rows w, w+8, ..., w+120; write back tf32 P
#pragma unroll
    for (int r = 0; r < 16; r++) {
        unsigned* rp = Ss + (warp + r * 8) * PMK;
        float x0 = __uint_as_float(rp[lane]);
        float x1 = __uint_as_float(rp[lane + 32]);
        float x2 = __uint_as_float(rp[lane + 64]);
        float x3 = __uint_as_float(rp[lane + 96]);
        float mx = fmaxf(fmaxf(x0, x1), fmaxf(x2, x3));
#pragma unroll
        for (int o = 16; o > 0; o >>= 1)
            mx = fmaxf(mx, __shfl_xor_sync(0xffffffffu, mx, o));
        float e0 = __expf(x0 - mx), e1 = __expf(x1 - mx);
        float e2 = __expf(x2 - mx), e3 = __expf(x3 - mx);
        float s = e0 + e1 + e2 + e3;
#pragma unroll
        for (int o = 16; o > 0; o >>= 1)
            s += __shfl_xor_sync(0xffffffffu, s, o);
        float inv = 1.0f / s;
        rp[lane]      = f2tf32(e0 * inv);
        rp[lane + 32] = f2tf32(e1 * inv);
        rp[lane + 64] = f2tf32(e2 * inv);
        rp[lane + 96] = f2tf32(e3 * inv);
    }
    __syncthreads();

    // ---- O^T[d][i] = sum_j V[d][j] P[i][j]; warps tile 64x128 as 2x4 of 32x32
    {
        const int mw = (warp >> 2) * 32;   // d offset
        const int nw = (warp & 3) * 32;    // i offset
        float acc[2][4][4];
#pragma unroll
        for (int mi = 0; mi < 2; mi++)
#pragma unroll
            for (int ni = 0; ni < 4; ni++)
#pragma unroll
                for (int r = 0; r < 4; r++) acc[mi][ni][r] = 0.0f;

#pragma unroll
        for (int ks = 0; ks < 16; ks++) {
            const int kb = ks * 8;
            unsigned a[2][4], bf[4][2];
#pragma unroll
            for (int mi = 0; mi < 2; mi++) {
                int dr = mw + mi * 16 + grp;
                a[mi][0] = Vs[dr * PMK + kb + qid];
                a[mi][1] = Vs[(dr + 8) * PMK + kb + qid];
                a[mi][2] = Vs[dr * PMK + kb + qid + 4];
                a[mi][3] = Vs[(dr + 8) * PMK + kb + qid + 4];
            }
#pragma unroll
            for (int ni = 0; ni < 4; ni++) {
                int ir = nw + ni * 8 + grp;
                bf[ni][0] = Ss[ir * PMK + kb + qid];
                bf[ni][1] = Ss[ir * PMK + kb + qid + 4];
            }
#pragma unroll
            for (int mi = 0; mi < 2; mi++)
#pragma unroll
                for (int ni = 0; ni < 4; ni++) {
                    asm volatile(
                        "mma.sync.aligned.m16n8k8.row.col.f32.tf32.tf32.f32 "
                        "{%0,%1,%2,%3}, {%4,%5,%6,%7}, {%8,%9}, {%0,%1,%2,%3};\n"
                        : "+f"(acc[mi][ni][0]), "+f"(acc[mi][ni][1]),
                          "+f"(acc[mi][ni][2]), "+f"(acc[mi][ni][3])
                        : "r"(a[mi][0]), "r"(a[mi][1]), "r"(a[mi][2]), "r"(a[mi][3]),
                          "r"(bf[ni][0]), "r"(bf[ni][1]));
                }
        }
        // stage O^T into Qs region (free now), layout [64][PKM]
        float* Os = (float*)Qs;
#pragma unroll
        for (int mi = 0; mi < 2; mi++) {
            int dr = mw + mi * 16 + grp;
#pragma unroll
            for (int ni = 0; ni < 4; ni++) {
                int ic = nw + ni * 8 + 2 * qid;
                *(float2*)&Os[dr * PKM + ic] =
                    make_float2(acc[mi][ni][0], acc[mi][ni][1]);
                *(float2*)&Os[(dr + 8) * PKM + ic] =
                    make_float2(acc[mi][ni][2], acc[mi][ni][3]);
            }
        }
    }
    __syncthreads();

    // coalesced store
    const float* Os = (const float*)Qs;
#pragma unroll
    for (int it = 0; it < 32; it++) {
        int idx = it * 256 + tid;
        int d = idx >> 7, i = idx & 127;
        attout[base + (long)d * NTOT + i] = Os[d * PKM + i];
    }
}

// ---------------------------------------------------------------------------
extern "C" void kernel_launch(void* const* d_in, const int* in_sizes, int n_in,
                              void* d_out, int out_size)
{
    const float* xs   = (const float*)d_in[0];
    const float* Wq_h = (const float*)d_in[1];
    const float* Wk_h = (const float*)d_in[2];
    const float* Wv_h = (const float*)d_in[3];
    const float* Wo_h = (const float*)d_in[4];
    const float* Wq_w = (const float*)d_in[5];
    const float* Wk_w = (const float*)d_in[6];
    const float* Wv_w = (const float*)d_in[7];
    const float* Wo_w = (const float*)d_in[8];
    float* out = (float*)d_out;

    float *qkv = nullptr, *att = nullptr, *tmp = nullptr;
    cudaGetSymbolAddress((void**)&qkv, g_qkv);
    cudaGetSymbolAddress((void**)&att, g_att);
    cudaGetSymbolAddress((void**)&tmp, g_tmp);

    cudaFuncSetAttribute(attn_tc_kernel,
                         cudaFuncAttributeMaxDynamicSharedMemorySize,
                         ATTN_SMEM_BYTES);

    dim3 gproj(NTOT / BN, CC / BM, 3);
    dim3 gout (NTOT / BN, CC / BM, 1);
    dim3 gattn(128, 8, 8);
    dim3 gtr(4, 4, BSZ * CC);
    dim3 btr(32, 8);

    // ---- height branch on transposed planes (seq = h, contiguous) ----
    transpose_hw_kernel<<<gtr, btr>>>(xs, tmp, nullptr);          // xt
    tgemm_kernel<<<gproj, 256>>>(Wq_h, Wk_h, Wv_h, tmp, qkv, nullptr, 0, 0);
    attn_tc_kernel<<<gattn, 256, ATTN_SMEM_BYTES>>>(qkv, att);
    tgemm_kernel<<<gout, 256>>>(Wo_h, Wo_h, Wo_h, att, tmp, nullptr, 1, 1); // oh_t
    transpose_hw_kernel<<<gtr, btr>>>(tmp, out, xs);              // out = xs + T(oh_t)

    // ---- width branch (seq = w, contiguous natively) ----
    tgemm_kernel<<<gproj, 256>>>(Wq_w, Wk_w, Wv_w, xs, qkv, nullptr, 0, 0);
    attn_tc_kernel<<<gattn, 256, ATTN_SMEM_BYTES>>>(qkv, att);
    tgemm_kernel<<<gout, 256>>>(Wo_w, Wo_w, Wo_w, att, out, out, 1, 1);
}